// round 1
// baseline (speedup 1.0000x reference)
#include <cuda_runtime.h>

// Row size in elements: C*W*H = 512*7*7 (fixed for this problem's metadata).
#define ROW_ELEMS 25088
#define ROW_VEC4  (ROW_ELEMS / 4)   // 6272 float4 per row

// Index table: g_src[3*p + j] = input row feeding output row (3*p + j).
// Max pairs supported: 8192 (actual P = 1920).
__device__ int g_src[3 * 8192];

// One block per image: compute prefix offsets over previous images, then
// fill this image's pair rows in parallel.
__global__ void build_idx_kernel(const int* __restrict__ obj_num, int n_images) {
    int b = blockIdx.x;
    if (b >= n_images) return;

    // Prefix sums over previous images (n_images is tiny: 16).
    int row_begin = 0;   // input-row offset of this image's chunk
    int pair_base = 0;   // global pair index offset
    for (int i = 0; i < b; ++i) {
        int ni = obj_num[i];
        row_begin += ni * (ni + 1) / 2;
        pair_base += ni * (ni - 1) / 2;
    }
    int n = obj_num[b];
    int T = n * (n - 1) / 2;

    for (int u = threadIdx.x; u < T; u += blockDim.x) {
        // Invert row-major upper-triangular enumeration: find o1 such that
        // S(o1) <= u < S(o1+1), S(o1) = o1*(n-1) - o1*(o1-1)/2.
        int o1 = 0;
        int s = 0;                 // S(o1)
        while (s + (n - 1 - o1) <= u) {
            s += (n - 1 - o1);
            ++o1;
        }
        int o2 = o1 + 1 + (u - s);

        int p = pair_base + u;
        g_src[3 * p + 0] = row_begin + o1;
        g_src[3 * p + 1] = row_begin + o2;
        g_src[3 * p + 2] = row_begin + n + u;   // union feature row
    }
}

// One block per output row: vectorized float4 copy of 25088 floats.
__global__ void __launch_bounds__(256) gather_rows_kernel(
    const float4* __restrict__ in, float4* __restrict__ out) {
    long long r = blockIdx.x;                 // output row index = 3*p + j
    int s = g_src[r];                         // source input row
    const float4* __restrict__ src = in + (long long)s * ROW_VEC4;
    float4* __restrict__ dst = out + r * ROW_VEC4;
    #pragma unroll 4
    for (int i = threadIdx.x; i < ROW_VEC4; i += 256) {
        dst[i] = src[i];
    }
}

extern "C" void kernel_launch(void* const* d_in, const int* in_sizes, int n_in,
                              void* d_out, int out_size) {
    const float* feats = (const float*)d_in[0];
    // d_in[1] is batch_size (scalar int) — batch count also equals len(obj_num).
    const int* obj_num = (const int*)d_in[2];
    int n_images = in_sizes[2];

    int out_rows = out_size / ROW_ELEMS;      // = 3 * P (5760)

    build_idx_kernel<<<n_images, 128>>>(obj_num, n_images);
    gather_rows_kernel<<<out_rows, 256>>>((const float4*)feats, (float4*)d_out);
}